// round 12
// baseline (speedup 1.0000x reference)
#include <cuda_runtime.h>
#include <cstdint>

#define NN   4
#define C    256
#define H    64
#define W    64
#define P    (H*W)
#define CCH  64
#define K2   25
#define HO   128
#define WO   128
#define ENC  100

typedef unsigned long long u64;
typedef unsigned int u32;

__device__ __forceinline__ u64 pack2(float lo, float hi) {
    u64 r; asm("mov.b64 %0, {%1,%2};" : "=l"(r) : "f"(lo), "f"(hi)); return r;
}
__device__ __forceinline__ u64 dup2(float v) {
    u64 r; asm("mov.b64 %0, {%1,%1};" : "=l"(r) : "f"(v)); return r;
}
__device__ __forceinline__ void unpack2(u64 v, float& lo, float& hi) {
    asm("mov.b64 {%0,%1}, %2;" : "=f"(lo), "=f"(hi) : "l"(v));
}
__device__ __forceinline__ u64 fma2(u64 a, u64 b, u64 c) {
    u64 d; asm("fma.rn.f32x2 %0, %1, %2, %3;" : "=l"(d) : "l"(a), "l"(b), "l"(c)); return d;
}
__device__ __forceinline__ u64 add2(u64 a, u64 b) {
    u64 d; asm("add.rn.f32x2 %0, %1, %2;" : "=l"(d) : "l"(a), "l"(b)); return d;
}
__device__ __forceinline__ void cp4(u32 dst, const float* src) {
    asm volatile("cp.async.ca.shared.global [%0], [%1], 4;" :: "r"(dst), "l"(src));
}
__device__ __forceinline__ void cp16(u32 dst, const float* src) {
    asm volatile("cp.async.cg.shared.global [%0], [%1], 16;" :: "r"(dst), "l"(src));
}

// scratch (device globals; no allocations allowed)
__device__ float g_comp[NN*CCH*P];           // 4 MB
__device__ float g_m[NN*ENC*P];              // 6.5 MB encoder logits
__device__ float g_wt[C*CCH];                // transposed compressor weights
__device__ float2 g_wp[4*8*8*9*14];          // packed encoder weights

// ---------------------------------------------------------------------------
// Kernel T: transpose Wc (64,256) -> g_wt (256,64)
// ---------------------------------------------------------------------------
__global__ void k_transpose(const float* __restrict__ Wc) {
    int idx = blockIdx.x * 256 + threadIdx.x;
    int oc = idx & 63, c = idx >> 6;
    g_wt[c*CCH + oc] = Wc[oc*C + c];
}

// ---------------------------------------------------------------------------
// Kernel P: pack encoder weights: We[100][64][9] ->
// g_wp[ocg 4][round 8][c 8][tap 9][qq 14] float2 (oc pairs, last padded)
// ---------------------------------------------------------------------------
__global__ void k_wpack(const float* __restrict__ We) {
    int idx = blockIdx.x * 256 + threadIdx.x;    // 32256 entries
    if (idx >= 4*8*8*9*14) return;
    int qq  = idx % 14;
    int tap = (idx / 14) % 9;
    int c   = (idx / 126) % 8;
    int r   = (idx / 1008) % 8;
    int ocg = idx / 8064;
    int cs  = r*8 + c;
    int oc  = ocg*25 + 2*qq;
    float wa = (2*qq     < 25) ? We[(oc*CCH + cs)*9 + tap]       : 0.f;
    float wb = (2*qq + 1 < 25) ? We[((oc + 1)*CCH + cs)*9 + tap] : 0.f;
    g_wp[idx] = make_float2(wa, wb);
}

// ---------------------------------------------------------------------------
// Kernel A: 1x1 conv compressor, 64oc x 32px tiles, packed f32x2 over px.
// ---------------------------------------------------------------------------
__global__ __launch_bounds__(128)
void k_compress(const float* __restrict__ x, const float* __restrict__ bc) {
    __shared__ __align__(16) float Ws[16][64];
    __shared__ __align__(16) float Xs[16][32];
    const int n  = blockIdx.y;
    const int p0 = blockIdx.x * 32;
    const int tx = threadIdx.x & 7;
    const int ty = threadIdx.x >> 3;

    u64 acc[4][2];
#pragma unroll
    for (int i = 0; i < 4; i++) { acc[i][0] = 0ull; acc[i][1] = 0ull; }

    for (int c0 = 0; c0 < C; c0 += 16) {
        __syncthreads();
        for (int i = threadIdx.x; i < 1024; i += 128) {
            int k = i >> 6, oc = i & 63;
            Ws[k][oc] = g_wt[(c0 + k)*CCH + oc];
        }
        for (int i = threadIdx.x; i < 512; i += 128) {
            int k = i >> 5, px = i & 31;
            Xs[k][px] = x[(n*C + c0 + k)*P + p0 + px];
        }
        __syncthreads();
#pragma unroll
        for (int k = 0; k < 16; k++) {
            float4 a = *(const float4*)&Ws[k][ty*4];
            u64 b01 = *(const u64*)&Xs[k][tx*4];
            u64 b23 = *(const u64*)&Xs[k][tx*4 + 2];
            float av[4] = {a.x, a.y, a.z, a.w};
#pragma unroll
            for (int i = 0; i < 4; i++) {
                u64 d = dup2(av[i]);
                acc[i][0] = fma2(d, b01, acc[i][0]);
                acc[i][1] = fma2(d, b23, acc[i][1]);
            }
        }
    }
#pragma unroll
    for (int i = 0; i < 4; i++) {
        int oc = ty*4 + i;
        u64 bd = dup2(bc[oc]);
        float* p = &g_comp[(n*CCH + oc)*P + p0 + tx*4];
        *(u64*)p       = add2(acc[i][0], bd);
        *(u64*)(p + 2) = add2(acc[i][1], bd);
    }
}

// ---------------------------------------------------------------------------
// Kernel B: 3x3 conv encoder, cp.async double-buffered, 256 threads (1 px
// per thread -> 8 warps/block for latency hiding), 13 packed oc-pair accs.
// grid (16 tiles, 4 n, 4 ocg) = 256 blocks.
// ---------------------------------------------------------------------------
__global__ __launch_bounds__(256)
void k_encode(const float* __restrict__ be) {
    __shared__ __align__(16) float tile[2][8*324];    // [c][18][18]
    __shared__ __align__(16) float2 wgt2[2][8*9*14];  // [c][tap][14 pairs]
    const int bx = blockIdx.x;
    const int h0 = (bx >> 2) * 16;
    const int w0 = (bx & 3) * 16;
    const int n  = blockIdx.y;
    const int ocg = blockIdx.z;
    const int oc0 = ocg * 25;
    const int xx = threadIdx.x & 15;
    const int ty = threadIdx.x >> 4;   // 0..15

    // staging geometry (2 slots per thread, round-invariant)
    int sps[2]; bool oks[2];
#pragma unroll
    for (int j = 0; j < 2; j++) {
        int q = threadIdx.x + j*256;
        oks[j] = false; sps[j] = 0;
        if (q < 324) {
            int yy = q / 18, xw = q % 18;
            int gy = h0 + yy - 1, gx = w0 + xw - 1;
            if (gy >= 0 && gy < H && gx >= 0 && gx < W) {
                oks[j] = true; sps[j] = gy*W + gx;
            } else {
#pragma unroll
                for (int c = 0; c < 8; c++) {
                    tile[0][c*324 + q] = 0.f;
                    tile[1][c*324 + q] = 0.f;
                }
            }
        }
    }
    const float* cb = g_comp + n*CCH*P;
    const float* wb = (const float*)(g_wp + ocg*8064);

    u32 ta[2], wa[2];
    ta[0] = (u32)__cvta_generic_to_shared(&tile[0][0]);
    ta[1] = (u32)__cvta_generic_to_shared(&tile[1][0]);
    wa[0] = (u32)__cvta_generic_to_shared(&wgt2[0][0]);
    wa[1] = (u32)__cvta_generic_to_shared(&wgt2[1][0]);

    // stage round 0
#pragma unroll
    for (int j = 0; j < 2; j++) if (oks[j]) {
        int q = threadIdx.x + j*256;
#pragma unroll
        for (int c = 0; c < 8; c++)
            cp4(ta[0] + (c*324 + q)*4, cb + c*P + sps[j]);
    }
    for (int i = threadIdx.x; i < 504; i += 256)
        cp16(wa[0] + i*16, wb + i*4);
    asm volatile("cp.async.commit_group;");

    u64 acc[13];
#pragma unroll
    for (int q = 0; q < 13; q++) acc[q] = 0ull;

    for (int r = 0; r < 8; r++) {
        asm volatile("cp.async.wait_group 0;");
        __syncthreads();
        if (r < 7) {
            int nb = (r + 1) & 1;
            const float* cbn = cb + (r + 1)*8*P;
#pragma unroll
            for (int j = 0; j < 2; j++) if (oks[j]) {
                int q = threadIdx.x + j*256;
#pragma unroll
                for (int c = 0; c < 8; c++)
                    cp4(ta[nb] + (c*324 + q)*4, cbn + c*P + sps[j]);
            }
            const float* wbn = wb + (r + 1)*2016;
            for (int i = threadIdx.x; i < 504; i += 256)
                cp16(wa[nb] + i*16, wbn + i*4);
            asm volatile("cp.async.commit_group;");
        }
        const float* tb = tile[r & 1];
        const float2* wg = wgt2[r & 1];
#pragma unroll 1
        for (int c = 0; c < 8; c++) {
            const int base = c*324 + ty*18 + xx;
#pragma unroll
            for (int ky = 0; ky < 3; ky++) {
                u64 dv[3];
                dv[0] = dup2(tb[base + ky*18]);
                dv[1] = dup2(tb[base + ky*18 + 1]);
                dv[2] = dup2(tb[base + ky*18 + 2]);
#pragma unroll
                for (int kx = 0; kx < 3; kx++) {
                    u64 v0 = dv[kx];
                    const float2* wp = &wg[(c*9 + ky*3 + kx)*14];
                    ulonglong2 w01 = *(const ulonglong2*)(wp);
                    ulonglong2 w23 = *(const ulonglong2*)(wp + 2);
                    ulonglong2 w45 = *(const ulonglong2*)(wp + 4);
                    ulonglong2 w67 = *(const ulonglong2*)(wp + 6);
                    ulonglong2 w89 = *(const ulonglong2*)(wp + 8);
                    ulonglong2 wAB = *(const ulonglong2*)(wp + 10);
                    u64 wC = *(const u64*)(wp + 12);
                    acc[0]  = fma2(v0, w01.x, acc[0]);
                    acc[1]  = fma2(v0, w01.y, acc[1]);
                    acc[2]  = fma2(v0, w23.x, acc[2]);
                    acc[3]  = fma2(v0, w23.y, acc[3]);
                    acc[4]  = fma2(v0, w45.x, acc[4]);
                    acc[5]  = fma2(v0, w45.y, acc[5]);
                    acc[6]  = fma2(v0, w67.x, acc[6]);
                    acc[7]  = fma2(v0, w67.y, acc[7]);
                    acc[8]  = fma2(v0, w89.x, acc[8]);
                    acc[9]  = fma2(v0, w89.y, acc[9]);
                    acc[10] = fma2(v0, wAB.x, acc[10]);
                    acc[11] = fma2(v0, wAB.y, acc[11]);
                    acc[12] = fma2(v0, wC,    acc[12]);
                }
            }
        }
        __syncthreads();
    }

    const int y = h0 + ty, xpx = w0 + xx;
    float* op = &g_m[n*ENC*P + y*W + xpx];
#pragma unroll
    for (int q = 0; q < 13; q++) {
        int oc = oc0 + 2*q;
        float a0, a1;
        unpack2(acc[q], a0, a1);
        op[oc*P] = a0 + be[oc];
        if (2*q + 1 < 25) op[(oc + 1)*P] = a1 + be[oc + 1];
    }
}

// ---------------------------------------------------------------------------
// Kernel D: fused softmax + reassembly. Masks for ALL 4 subpixels packed in
// smem u64 arrays (shuffle-packed once); tap loop split 13+12 so only 26 u64
// mask regs live at a time -> no spills. Per tap per channel:
// 1 LDS.32 + 1 dup + 2 fma2 (1 B smem / MAC). cp.async double-buffered x.
// grid (64 tiles, 4 n, 4 cgrp) = 1024 blocks x 256 thr.
// ---------------------------------------------------------------------------
__global__ __launch_bounds__(256)
void k_reassemble(const float* __restrict__ x, float* __restrict__ out) {
    __shared__ u64 msbuf[25*66*2];     // 26.4KB: logits (float alias) -> masks
    __shared__ float xs[2][16*168];    // 21.5KB
    float* msf = (float*)msbuf;
    u64* mp01 = msbuf;                 // [k][66] subs {0,1}
    u64* mp23 = msbuf + 25*66;         // [k][66] subs {2,3}

    const int t   = blockIdx.x;
    const int n   = blockIdx.y;
    const int c00 = blockIdx.z * 64;
    const int h0 = (t >> 3) * 8, w0 = (t & 7) * 8;
    const int cl = threadIdx.x & 3;
    const int p  = threadIdx.x >> 2;
    const int h  = p >> 3, w = p & 7;
    const int gh = h0 + h, gw = w0 + w;

    // staging geometry + boundary pre-zero
    int sp = -1;
    if (threadIdx.x < 144) {
        int yy = threadIdx.x / 12, xw = threadIdx.x % 12;
        int gy = h0 + yy - 2, gx = w0 + xw - 2;
        if (gy >= 0 && gy < H && gx >= 0 && gx < W) sp = gy*W + gx;
        if (sp < 0) {
#pragma unroll
            for (int c = 0; c < 16; c++) {
                xs[0][c*168 + threadIdx.x] = 0.f;
                xs[1][c*168 + threadIdx.x] = 0.f;
            }
        }
    }
    const float* xb = x + (n*C + c00)*P + (sp < 0 ? 0 : sp);
    u32 xsa[2];
    xsa[0] = (u32)__cvta_generic_to_shared(&xs[0][threadIdx.x]);
    xsa[1] = (u32)__cvta_generic_to_shared(&xs[1][threadIdx.x]);

    if (sp >= 0) {
#pragma unroll
        for (int c = 0; c < 16; c++) cp4(xsa[0] + c*168*4, xb + c*P);
    }
    asm volatile("cp.async.commit_group;");

    // stage encoder logits
    for (int idx = threadIdx.x; idx < ENC*64; idx += 256) {
        int ch = idx >> 6, pp = idx & 63;
        msf[ch*65 + pp] = g_m[(n*ENC + ch)*P + (h0 + (pp>>3))*W + w0 + (pp&7)];
    }
    __syncthreads();

    // softmax into registers: thread -> (pixel p, sub cl)
    float tv[25];
    {
        float mx = -1e30f;
#pragma unroll
        for (int k = 0; k < 25; k++) {
            tv[k] = msf[(k*4 + cl)*65 + p];
            mx = fmaxf(mx, tv[k]);
        }
        float sum = 0.f;
#pragma unroll
        for (int k = 0; k < 25; k++) { tv[k] = __expf(tv[k] - mx); sum += tv[k]; }
        float inv = 1.f / sum;
#pragma unroll
        for (int k = 0; k < 25; k++) tv[k] *= inv;
    }
    __syncthreads();   // all reads of msf (float layout) done

    // shuffle-pack masks into u64 layout
#pragma unroll
    for (int k = 0; k < 25; k++) {
        float part = __shfl_xor_sync(0xffffffffu, tv[k], 1);
        if (cl == 0)      mp01[k*66 + p] = pack2(tv[k], part);
        else if (cl == 2) mp23[k*66 + p] = pack2(tv[k], part);
    }
    __syncthreads();

    float* ob = out + (size_t)(n*C + c00)*HO*WO + (size_t)(2*gh)*WO + 2*gw;
    const int xoff = h*12 + w;

    for (int rr = 0; rr < 4; rr++) {
        asm volatile("cp.async.wait_group 0;");
        __syncthreads();
        if (rr < 3) {
            if (sp >= 0) {
                const float* src = xb + (rr + 1)*16*P;
                u32 d = xsa[(rr + 1) & 1];
#pragma unroll
                for (int c = 0; c < 16; c++) cp4(d + c*168*4, src + c*P);
            }
            asm volatile("cp.async.commit_group;");
        }
        const float* xsb = xs[rr & 1];

        u64 a01[4], a23[4];
#pragma unroll
        for (int j = 0; j < 4; j++) { a01[j] = 0ull; a23[j] = 0ull; }

#pragma unroll
        for (int half = 0; half < 2; half++) {
            const int kb = half ? 13 : 0;
            const int kn = half ? 12 : 13;
            u64 m01[13], m23[13];
#pragma unroll
            for (int k = 0; k < 13; k++) {
                if (k < kn) {
                    m01[k] = mp01[(kb + k)*66 + p];
                    m23[k] = mp23[(kb + k)*66 + p];
                }
            }
#pragma unroll
            for (int cc = 0; cc < 4; cc++) {
                int c = cl + cc*4;             // banks 8cl+w: conflict-free
                const float* xp = &xsb[c*168 + xoff];
#pragma unroll
                for (int k = 0; k < 13; k++) {
                    if (k < kn) {
                        int kk = kb + k;
                        u64 vd = dup2(xp[(kk/5)*12 + (kk%5)]);
                        a01[cc] = fma2(vd, m01[k], a01[cc]);
                        a23[cc] = fma2(vd, m23[k], a23[cc]);
                    }
                }
            }
        }
#pragma unroll
        for (int cc = 0; cc < 4; cc++) {
            float* o = ob + (size_t)(rr*16 + cl + cc*4)*HO*WO;
            *(u64*)o        = a01[cc];
            *(u64*)(o + WO) = a23[cc];
        }
    }
}

// ---------------------------------------------------------------------------
extern "C" void kernel_launch(void* const* d_in, const int* in_sizes, int n_in,
                              void* d_out, int out_size) {
    const float* x  = (const float*)d_in[0];
    const float* Wc = (const float*)d_in[1];
    const float* bc = (const float*)d_in[2];
    const float* We = (const float*)d_in[3];
    const float* be = (const float*)d_in[4];
    float* out = (float*)d_out;

    k_transpose <<<64, 256>>>(Wc);
    k_wpack     <<<126, 256>>>(We);
    k_compress  <<<dim3(128, NN), 128>>>(x, bc);
    k_encode    <<<dim3(16, NN, 4), 256>>>(be);
    k_reassemble<<<dim3(64, NN, 4), 256>>>(x, out);
}

// round 13
// speedup vs baseline: 1.2238x; 1.2238x over previous
#include <cuda_runtime.h>
#include <cstdint>

#define NN   4
#define C    256
#define H    64
#define W    64
#define P    (H*W)
#define CCH  64
#define K2   25
#define HO   128
#define WO   128
#define ENC  100

typedef unsigned long long u64;
typedef unsigned int u32;

__device__ __forceinline__ u64 pack2(float lo, float hi) {
    u64 r; asm("mov.b64 %0, {%1,%2};" : "=l"(r) : "f"(lo), "f"(hi)); return r;
}
__device__ __forceinline__ u64 dup2(float v) {
    u64 r; asm("mov.b64 %0, {%1,%1};" : "=l"(r) : "f"(v)); return r;
}
__device__ __forceinline__ void unpack2(u64 v, float& lo, float& hi) {
    asm("mov.b64 {%0,%1}, %2;" : "=f"(lo), "=f"(hi) : "l"(v));
}
__device__ __forceinline__ u64 fma2(u64 a, u64 b, u64 c) {
    u64 d; asm("fma.rn.f32x2 %0, %1, %2, %3;" : "=l"(d) : "l"(a), "l"(b), "l"(c)); return d;
}
__device__ __forceinline__ u64 add2(u64 a, u64 b) {
    u64 d; asm("add.rn.f32x2 %0, %1, %2;" : "=l"(d) : "l"(a), "l"(b)); return d;
}
__device__ __forceinline__ void cp4(u32 dst, const float* src) {
    asm volatile("cp.async.ca.shared.global [%0], [%1], 4;" :: "r"(dst), "l"(src));
}
__device__ __forceinline__ void cp16(u32 dst, const float* src) {
    asm volatile("cp.async.cg.shared.global [%0], [%1], 16;" :: "r"(dst), "l"(src));
}

// scratch (device globals; no allocations allowed)
__device__ float g_comp[NN*CCH*P];           // 4 MB
__device__ float g_m[NN*ENC*P];              // encoder logits, K-half 0
__device__ float g_m2[NN*ENC*P];             // encoder logits, K-half 1
__device__ float g_wt[C*CCH];                // transposed compressor weights
__device__ float2 g_wp[4*8*8*9*14];          // packed encoder weights

// ---------------------------------------------------------------------------
// Kernel T: transpose Wc (64,256) -> g_wt (256,64)
// ---------------------------------------------------------------------------
__global__ void k_transpose(const float* __restrict__ Wc) {
    int idx = blockIdx.x * 256 + threadIdx.x;
    int oc = idx & 63, c = idx >> 6;
    g_wt[c*CCH + oc] = Wc[oc*C + c];
}

// ---------------------------------------------------------------------------
// Kernel P: pack encoder weights: We[100][64][9] ->
// g_wp[ocg 4][round 8][c 8][tap 9][qq 14] float2 (oc pairs, last padded)
// ---------------------------------------------------------------------------
__global__ void k_wpack(const float* __restrict__ We) {
    int idx = blockIdx.x * 256 + threadIdx.x;    // 32256 entries
    if (idx >= 4*8*8*9*14) return;
    int qq  = idx % 14;
    int tap = (idx / 14) % 9;
    int c   = (idx / 126) % 8;
    int r   = (idx / 1008) % 8;
    int ocg = idx / 8064;
    int cs  = r*8 + c;
    int oc  = ocg*25 + 2*qq;
    float wa = (2*qq     < 25) ? We[(oc*CCH + cs)*9 + tap]       : 0.f;
    float wb = (2*qq + 1 < 25) ? We[((oc + 1)*CCH + cs)*9 + tap] : 0.f;
    g_wp[idx] = make_float2(wa, wb);
}

// ---------------------------------------------------------------------------
// Kernel A: 1x1 conv compressor, 64oc x 32px tiles, packed f32x2 over px.
// ---------------------------------------------------------------------------
__global__ __launch_bounds__(128)
void k_compress(const float* __restrict__ x, const float* __restrict__ bc) {
    __shared__ __align__(16) float Ws[16][64];
    __shared__ __align__(16) float Xs[16][32];
    const int n  = blockIdx.y;
    const int p0 = blockIdx.x * 32;
    const int tx = threadIdx.x & 7;
    const int ty = threadIdx.x >> 3;

    u64 acc[4][2];
#pragma unroll
    for (int i = 0; i < 4; i++) { acc[i][0] = 0ull; acc[i][1] = 0ull; }

    for (int c0 = 0; c0 < C; c0 += 16) {
        __syncthreads();
        for (int i = threadIdx.x; i < 1024; i += 128) {
            int k = i >> 6, oc = i & 63;
            Ws[k][oc] = g_wt[(c0 + k)*CCH + oc];
        }
        for (int i = threadIdx.x; i < 512; i += 128) {
            int k = i >> 5, px = i & 31;
            Xs[k][px] = x[(n*C + c0 + k)*P + p0 + px];
        }
        __syncthreads();
#pragma unroll
        for (int k = 0; k < 16; k++) {
            float4 a = *(const float4*)&Ws[k][ty*4];
            u64 b01 = *(const u64*)&Xs[k][tx*4];
            u64 b23 = *(const u64*)&Xs[k][tx*4 + 2];
            float av[4] = {a.x, a.y, a.z, a.w};
#pragma unroll
            for (int i = 0; i < 4; i++) {
                u64 d = dup2(av[i]);
                acc[i][0] = fma2(d, b01, acc[i][0]);
                acc[i][1] = fma2(d, b23, acc[i][1]);
            }
        }
    }
#pragma unroll
    for (int i = 0; i < 4; i++) {
        int oc = ty*4 + i;
        u64 bd = dup2(bc[oc]);
        float* p = &g_comp[(n*CCH + oc)*P + p0 + tx*4];
        *(u64*)p       = add2(acc[i][0], bd);
        *(u64*)(p + 2) = add2(acc[i][1], bd);
    }
}

// ---------------------------------------------------------------------------
// Kernel B: 3x3 conv encoder. R11's optimal mix (128 thr, 2px/thread, 13
// packed oc-pair accs) + K-split across grid (kh: 32 ch each) for 2x warp
// parallelism + cp.async double-buffered staging.
// grid (16 tiles, 4 n, 4 ocg x 2 kh) = 512 blocks x 128 thr.
// ---------------------------------------------------------------------------
__global__ __launch_bounds__(128)
void k_encode(const float* __restrict__ be) {
    __shared__ __align__(16) float tile[2][8*324];    // [c][18][18]
    __shared__ __align__(16) float2 wgt2[2][8*9*14];  // [c][tap][14 pairs]
    const int bx = blockIdx.x;
    const int h0 = (bx >> 2) * 16;
    const int w0 = (bx & 3) * 16;
    const int n  = blockIdx.y;
    const int ocg = blockIdx.z & 3;
    const int kh  = blockIdx.z >> 2;
    const int oc0 = ocg * 25;
    const int xg = threadIdx.x & 7;
    const int ty = threadIdx.x >> 3;   // 0..15

    // staging geometry (3 slots per thread, round-invariant)
    int sps[3]; bool oks[3];
#pragma unroll
    for (int j = 0; j < 3; j++) {
        int q = threadIdx.x + j*128;
        oks[j] = false; sps[j] = 0;
        if (q < 324) {
            int yy = q / 18, xw = q % 18;
            int gy = h0 + yy - 1, gx = w0 + xw - 1;
            if (gy >= 0 && gy < H && gx >= 0 && gx < W) {
                oks[j] = true; sps[j] = gy*W + gx;
            } else {
#pragma unroll
                for (int c = 0; c < 8; c++) {
                    tile[0][c*324 + q] = 0.f;
                    tile[1][c*324 + q] = 0.f;
                }
            }
        }
    }
    const float* cb = g_comp + n*CCH*P + kh*32*P;
    const float* wb = (const float*)(g_wp + ocg*8064 + kh*4032);

    u32 ta[2], wa[2];
    ta[0] = (u32)__cvta_generic_to_shared(&tile[0][0]);
    ta[1] = (u32)__cvta_generic_to_shared(&tile[1][0]);
    wa[0] = (u32)__cvta_generic_to_shared(&wgt2[0][0]);
    wa[1] = (u32)__cvta_generic_to_shared(&wgt2[1][0]);

    // stage round 0
#pragma unroll
    for (int j = 0; j < 3; j++) if (oks[j]) {
        int q = threadIdx.x + j*128;
#pragma unroll
        for (int c = 0; c < 8; c++)
            cp4(ta[0] + (c*324 + q)*4, cb + c*P + sps[j]);
    }
    for (int i = threadIdx.x; i < 504; i += 128)
        cp16(wa[0] + i*16, wb + i*4);
    asm volatile("cp.async.commit_group;");

    u64 accA[13], accB[13];
#pragma unroll
    for (int q = 0; q < 13; q++) { accA[q] = 0ull; accB[q] = 0ull; }

    for (int r = 0; r < 4; r++) {
        asm volatile("cp.async.wait_group 0;");
        __syncthreads();
        if (r < 3) {
            int nb = (r + 1) & 1;
            const float* cbn = cb + (r + 1)*8*P;
#pragma unroll
            for (int j = 0; j < 3; j++) if (oks[j]) {
                int q = threadIdx.x + j*128;
#pragma unroll
                for (int c = 0; c < 8; c++)
                    cp4(ta[nb] + (c*324 + q)*4, cbn + c*P + sps[j]);
            }
            const float* wbn = wb + (r + 1)*2016;
            for (int i = threadIdx.x; i < 504; i += 128)
                cp16(wa[nb] + i*16, wbn + i*4);
            asm volatile("cp.async.commit_group;");
        }
        const float* tb = tile[r & 1];
        const float2* wg = wgt2[r & 1];
#pragma unroll 1
        for (int c = 0; c < 8; c++) {
            const int base = c*324 + ty*18 + xg*2;
#pragma unroll
            for (int ky = 0; ky < 3; ky++) {
                float2 fa = *(const float2*)&tb[base + ky*18];
                float2 fb = *(const float2*)&tb[base + ky*18 + 2];
                u64 dv[4];
                dv[0] = dup2(fa.x); dv[1] = dup2(fa.y);
                dv[2] = dup2(fb.x); dv[3] = dup2(fb.y);
#pragma unroll
                for (int kx = 0; kx < 3; kx++) {
                    u64 v0 = dv[kx];
                    u64 v1 = dv[kx + 1];
                    const float2* wp = &wg[(c*9 + ky*3 + kx)*14];
                    ulonglong2 w01 = *(const ulonglong2*)(wp);
                    ulonglong2 w23 = *(const ulonglong2*)(wp + 2);
                    ulonglong2 w45 = *(const ulonglong2*)(wp + 4);
                    ulonglong2 w67 = *(const ulonglong2*)(wp + 6);
                    ulonglong2 w89 = *(const ulonglong2*)(wp + 8);
                    ulonglong2 wAB = *(const ulonglong2*)(wp + 10);
                    u64 wC = *(const u64*)(wp + 12);
                    accA[0]  = fma2(v0, w01.x, accA[0]);  accB[0]  = fma2(v1, w01.x, accB[0]);
                    accA[1]  = fma2(v0, w01.y, accA[1]);  accB[1]  = fma2(v1, w01.y, accB[1]);
                    accA[2]  = fma2(v0, w23.x, accA[2]);  accB[2]  = fma2(v1, w23.x, accB[2]);
                    accA[3]  = fma2(v0, w23.y, accA[3]);  accB[3]  = fma2(v1, w23.y, accB[3]);
                    accA[4]  = fma2(v0, w45.x, accA[4]);  accB[4]  = fma2(v1, w45.x, accB[4]);
                    accA[5]  = fma2(v0, w45.y, accA[5]);  accB[5]  = fma2(v1, w45.y, accB[5]);
                    accA[6]  = fma2(v0, w67.x, accA[6]);  accB[6]  = fma2(v1, w67.x, accB[6]);
                    accA[7]  = fma2(v0, w67.y, accA[7]);  accB[7]  = fma2(v1, w67.y, accB[7]);
                    accA[8]  = fma2(v0, w89.x, accA[8]);  accB[8]  = fma2(v1, w89.x, accB[8]);
                    accA[9]  = fma2(v0, w89.y, accA[9]);  accB[9]  = fma2(v1, w89.y, accB[9]);
                    accA[10] = fma2(v0, wAB.x, accA[10]); accB[10] = fma2(v1, wAB.x, accB[10]);
                    accA[11] = fma2(v0, wAB.y, accA[11]); accB[11] = fma2(v1, wAB.y, accB[11]);
                    accA[12] = fma2(v0, wC,    accA[12]); accB[12] = fma2(v1, wC,    accB[12]);
                }
            }
        }
        __syncthreads();
    }

    float* __restrict__ gout = kh ? g_m2 : g_m;
    const int y = h0 + ty, xpx = w0 + xg*2;
#pragma unroll
    for (int q = 0; q < 13; q++) {
        int oc = oc0 + 2*q;
        float a0, a1, b0, b1;
        unpack2(accA[q], a0, a1);
        unpack2(accB[q], b0, b1);
        float bias0 = kh ? 0.f : be[oc];
        *(float2*)&gout[(n*ENC + oc)*P + y*W + xpx] = make_float2(a0 + bias0, b0 + bias0);
        if (2*q + 1 < 25) {
            float bias1 = kh ? 0.f : be[oc + 1];
            *(float2*)&gout[(n*ENC + oc + 1)*P + y*W + xpx] = make_float2(a1 + bias1, b1 + bias1);
        }
    }
}

// ---------------------------------------------------------------------------
// Kernel D: fused softmax + reassembly (R10 scheme W, g_m + g_m2 sum).
// ---------------------------------------------------------------------------
__global__ __launch_bounds__(256)
void k_reassemble(const float* __restrict__ x, float* __restrict__ out) {
    __shared__ float ms[ENC*65];
    __shared__ __align__(16) float xs[2][144*18];   // [spatial][ch pad 18]
    const int t   = blockIdx.x;
    const int n   = blockIdx.y;
    const int c00 = blockIdx.z * 64;
    const int h0 = (t >> 3) * 8, w0 = (t & 7) * 8;
    const int s  = threadIdx.x & 3;
    const int p  = threadIdx.x >> 2;
    const int h  = p >> 3, w = p & 7;
    const int gh = h0 + h, gw = w0 + w;
    const int si = s >> 1, sj = s & 1;

    int sp = -1;
    if (threadIdx.x < 144) {
        int yy = threadIdx.x / 12, xw = threadIdx.x % 12;
        int gy = h0 + yy - 2, gx = w0 + xw - 2;
        if (gy >= 0 && gy < H && gx >= 0 && gx < W) sp = gy*W + gx;
        if (sp < 0) {
#pragma unroll
            for (int c = 0; c < 16; c++) {
                xs[0][threadIdx.x*18 + c] = 0.f;
                xs[1][threadIdx.x*18 + c] = 0.f;
            }
        }
    }
    const float* xb = x + (n*C + c00)*P + (sp < 0 ? 0 : sp);
    u32 xsa[2];
    xsa[0] = (u32)__cvta_generic_to_shared(&xs[0][threadIdx.x*18]);
    xsa[1] = (u32)__cvta_generic_to_shared(&xs[1][threadIdx.x*18]);

    if (sp >= 0) {
#pragma unroll
        for (int c = 0; c < 16; c++) cp4(xsa[0] + c*4, xb + c*P);
    }
    asm volatile("cp.async.commit_group;");

    for (int idx = threadIdx.x; idx < ENC*64; idx += 256) {
        int ch = idx >> 6, pp = idx & 63;
        int src = (n*ENC + ch)*P + (h0 + (pp>>3))*W + w0 + (pp&7);
        ms[ch*65 + pp] = g_m[src] + g_m2[src];
    }
    __syncthreads();

    float mk[25];
    {
        float mx = -1e30f;
#pragma unroll
        for (int k = 0; k < 25; k++) {
            mk[k] = ms[(k*4 + s)*65 + p];
            mx = fmaxf(mx, mk[k]);
        }
        float sum = 0.f;
#pragma unroll
        for (int k = 0; k < 25; k++) { mk[k] = __expf(mk[k] - mx); sum += mk[k]; }
        float inv = 1.f / sum;
#pragma unroll
        for (int k = 0; k < 25; k++) mk[k] *= inv;
    }

    float* ob = out + (size_t)(n*C + c00)*HO*WO + (size_t)(2*gh + si)*WO + 2*gw + sj;
    const int xbase = (h*12 + w)*18;

    for (int rr = 0; rr < 4; rr++) {
        asm volatile("cp.async.wait_group 0;");
        __syncthreads();
        if (rr < 3) {
            if (sp >= 0) {
                const float* src = xb + (rr + 1)*16*P;
                u32 d = xsa[(rr + 1) & 1];
#pragma unroll
                for (int c = 0; c < 16; c++) cp4(d + c*4, src + c*P);
            }
            asm volatile("cp.async.commit_group;");
        }
        const float* xsb = xs[rr & 1] + xbase;

        u64 acc[8];
#pragma unroll
        for (int q = 0; q < 8; q++) acc[q] = 0ull;
#pragma unroll
        for (int k = 0; k < 25; k++) {
            const float* xp = xsb + ((k/5)*12 + (k%5))*18;
            u64 md = dup2(mk[k]);
#pragma unroll
            for (int q = 0; q < 8; q++)
                acc[q] = fma2(*(const u64*)(xp + q*2), md, acc[q]);
        }
#pragma unroll
        for (int q = 0; q < 8; q++) {
            float lo, hi;
            unpack2(acc[q], lo, hi);
            ob[(size_t)(rr*16 + 2*q)*HO*WO]     = lo;
            ob[(size_t)(rr*16 + 2*q + 1)*HO*WO] = hi;
        }
    }
}

// ---------------------------------------------------------------------------
extern "C" void kernel_launch(void* const* d_in, const int* in_sizes, int n_in,
                              void* d_out, int out_size) {
    const float* x  = (const float*)d_in[0];
    const float* Wc = (const float*)d_in[1];
    const float* bc = (const float*)d_in[2];
    const float* We = (const float*)d_in[3];
    const float* be = (const float*)d_in[4];
    float* out = (float*)d_out;

    k_transpose <<<64, 256>>>(Wc);
    k_wpack     <<<126, 256>>>(We);
    k_compress  <<<dim3(128, NN), 128>>>(x, bc);
    k_encode    <<<dim3(16, NN, 8), 128>>>(be);
    k_reassemble<<<dim3(64, NN, 4), 256>>>(x, out);
}